// round 10
// baseline (speedup 1.0000x reference)
#include <cuda_runtime.h>
#include <cuda_fp16.h>
#include <cstdint>

// Problem constants (match reference)
#define N_ATOMS   245760
#define N_PAIRS   16777216
#define N_MOLS    4096
#define KE_CONST  138.96f

#define THREADS   1024
#define BLOCKS    296          // 2 blocks/SM x 148 SMs = 64 warps/SM

// fp16 slice: atoms [0, S_SLICE) served from SMEM on the shared pipe.
// dyn smem = 4096*4 (hist) + 49152*2 (slice) = 114688 B/block; 2/SM fits.
#define S_SLICE   49152
#define SMEM_BYTES (N_MOLS * sizeof(float) + S_SLICE * sizeof(__half))

// ---------------------------------------------------------------------------
// Kernel 1: initialize output with per_system_energy * KE
// ---------------------------------------------------------------------------
__global__ void init_out_kernel(const float* __restrict__ pse,
                                float* __restrict__ out) {
    int m = blockIdx.x * blockDim.x + threadIdx.x;
    if (m < N_MOLS) out[m] = pse[m] * KE_CONST;
}

// ---------------------------------------------------------------------------
// chi(d) with the phi(2d) attenuation folded in
// ---------------------------------------------------------------------------
__device__ __forceinline__ float chi_of_d(float d) {
    float u  = 2.0f * d;
    float u2 = u * u;
    float u3 = u2 * u;
    float inner = fmaf(-6.0f, u2, fmaf(15.0f, u, -10.0f));
    float phi   = fmaf(u3, inner, 1.0f);
    phi = (u < 1.0f) ? phi : 0.0f;

    float rs = rsqrtf(fmaf(d, d, 1.0f));   // 1/sqrt(d^2+1)
    float rd = __fdividef(1.0f, d);        // 1/d
    return fmaf(phi, rs - rd, rd);         // rd + phi*(rs-rd)
}

// ---------------------------------------------------------------------------
// Branchless dual-space gather: @p LDS.b16 (shared pipe) else @!p LDG
// (global wavefronts only for active lanes). NO BSSY/BSYNC.
// ---------------------------------------------------------------------------
__device__ __forceinline__ float get_q(const float* __restrict__ q,
                                       unsigned int qs_addr, int i) {
    float v;
    asm volatile(
        "{\n\t"
        ".reg .pred p;\n\t"
        ".reg .b16  h;\n\t"
        ".reg .u32  sa;\n\t"
        ".reg .u64  ga;\n\t"
        "setp.lt.s32 p, %1, %4;\n\t"
        "mad.lo.u32  sa, %1, 2, %2;\n\t"
        "@p  ld.shared.b16 h, [sa];\n\t"
        "@p  cvt.f32.f16 %0, h;\n\t"
        "mul.wide.s32 ga, %1, 4;\n\t"
        "add.u64 ga, ga, %3;\n\t"
        "@!p ld.global.nc.f32 %0, [ga];\n\t"
        "}"
        : "=f"(v)
        : "r"(i), "r"(qs_addr), "l"(q), "n"(S_SLICE));
    return v;
}

// ---------------------------------------------------------------------------
// Kernel 2: R1 hot-loop structure + branchless 20% fp16 SMEM divert
// ---------------------------------------------------------------------------
__global__ __launch_bounds__(THREADS, 2)
void coulomb_pairs_kernel(const float* __restrict__ q,
                          const int*   __restrict__ idx_i,
                          const int*   __restrict__ idx_j,
                          const float* __restrict__ d_ij,
                          const int*   __restrict__ seg,
                          float*       __restrict__ out)
{
    extern __shared__ float smem[];
    float*  acc = smem;                                      // 16 KB histogram
    __half* qs  = reinterpret_cast<__half*>(smem + N_MOLS);  // 96 KB fp16 slice
    unsigned int qs_addr = (unsigned int)__cvta_generic_to_shared(qs);

    {
        float4* acc4 = reinterpret_cast<float4*>(acc);
        for (int m = threadIdx.x; m < N_MOLS / 4; m += THREADS)
            acc4[m] = make_float4(0.0f, 0.0f, 0.0f, 0.0f);
    }
    // Stage the low 49152 charges as fp16 (coalesced; table is L2-hot)
    for (int k = threadIdx.x; k < S_SLICE; k += THREADS)
        qs[k] = __float2half(q[k]);
    __syncthreads();

    const int nquads = N_PAIRS / 4;
    const int stride = gridDim.x * THREADS;

    for (int t = blockIdx.x * THREADS + threadIdx.x; t < nquads; t += stride) {
        // ---- Streaming loads (evict-first: keep L1 for gathers) ----
        int4   vi = __ldcs(reinterpret_cast<const int4*>(idx_i) + t);
        int4   vj = __ldcs(reinterpret_cast<const int4*>(idx_j) + t);
        float4 vd = __ldcs(reinterpret_cast<const float4*>(d_ij) + t);
        int4   vs = __ldcs(reinterpret_cast<const int4*>(seg)   + t);

        // ---- 8 branchless dual-space gathers, back-to-back ----
        float qi0 = get_q(q, qs_addr, vi.x), qj0 = get_q(q, qs_addr, vj.x);
        float qi1 = get_q(q, qs_addr, vi.y), qj1 = get_q(q, qs_addr, vj.y);
        float qi2 = get_q(q, qs_addr, vi.z), qj2 = get_q(q, qs_addr, vj.z);
        float qi3 = get_q(q, qs_addr, vi.w), qj3 = get_q(q, qs_addr, vj.w);

        // ---- Compute ----
        float c0 = qi0 * qj0 * chi_of_d(vd.x);
        float c1 = qi1 * qj1 * chi_of_d(vd.y);
        float c2 = qi2 * qj2 * chi_of_d(vd.z);
        float c3 = qi3 * qj3 * chi_of_d(vd.w);

        // ---- Scatter: single-statement if -> @P ATOMS (shared pipe) ----
        if (vi.x < vj.x) atomicAdd(&acc[vs.x], c0);
        if (vi.y < vj.y) atomicAdd(&acc[vs.y], c1);
        if (vi.z < vj.z) atomicAdd(&acc[vs.z], c2);
        if (vi.w < vj.w) atomicAdd(&acc[vs.w], c3);
    }

    __syncthreads();

    // Flush block-private histogram (out already holds pse*KE);
    // staggered CTA completion keeps these L2 atomics overlapped.
    for (int m = threadIdx.x; m < N_MOLS; m += THREADS) {
        float v = acc[m];
        if (v != 0.0f)
            atomicAdd(&out[m], v * KE_CONST);
    }
}

// ---------------------------------------------------------------------------
// Launch
// ---------------------------------------------------------------------------
extern "C" void kernel_launch(void* const* d_in, const int* in_sizes, int n_in,
                              void* d_out, int out_size) {
    const float* q    = (const float*)d_in[0];
    const int*   pidx = (const int*)  d_in[1];
    const float* dij  = (const float*)d_in[2];
    const int*   seg  = (const int*)  d_in[3];
    const float* pse  = (const float*)d_in[4];
    float* out = (float*)d_out;

    const int* idx_i = pidx;
    const int* idx_j = pidx + N_PAIRS;

    static bool attr_done = false;
    if (!attr_done) {
        cudaFuncSetAttribute(coulomb_pairs_kernel,
                             cudaFuncAttributeMaxDynamicSharedMemorySize,
                             (int)SMEM_BYTES);
        attr_done = true;
    }

    init_out_kernel<<<(N_MOLS + 255) / 256, 256>>>(pse, out);

    coulomb_pairs_kernel<<<BLOCKS, THREADS, SMEM_BYTES>>>(
        q, idx_i, idx_j, dij, seg, out);
}

// round 11
// speedup vs baseline: 2.2758x; 2.2758x over previous
#include <cuda_runtime.h>

// Problem constants (match reference)
#define N_ATOMS   245760
#define N_PAIRS   16777216
#define N_MOLS    4096
#define KE_CONST  138.96f

// ---------------------------------------------------------------------------
// Kernel 1: initialize output with per_system_energy * KE
// ---------------------------------------------------------------------------
__global__ void init_out_kernel(const float* __restrict__ pse,
                                float* __restrict__ out) {
    int m = blockIdx.x * blockDim.x + threadIdx.x;
    if (m < N_MOLS) out[m] = pse[m] * KE_CONST;
}

// ---------------------------------------------------------------------------
// chi(d) with the phi(2d) attenuation folded in
// ---------------------------------------------------------------------------
__device__ __forceinline__ float chi_of_d(float d) {
    // phi(u) = 1 - 6u^5 + 15u^4 - 10u^3, u = 2d, zero for u >= 1
    float u  = 2.0f * d;
    float u2 = u * u;
    float u3 = u2 * u;
    float inner = fmaf(-6.0f, u2, fmaf(15.0f, u, -10.0f));
    float phi   = fmaf(u3, inner, 1.0f);
    phi = (u < 1.0f) ? phi : 0.0f;

    float rs = rsqrtf(fmaf(d, d, 1.0f));   // 1/sqrt(d^2+1)
    float rd = __fdividef(1.0f, d);        // 1/d
    return fmaf(phi, rs - rd, rd);         // rd + phi*(rs-rd)
}

// ---------------------------------------------------------------------------
// Kernel 2: R1 hot loop verbatim; staggered-order flush epilogue
// ---------------------------------------------------------------------------
__global__ __launch_bounds__(512, 4)
void coulomb_pairs_kernel(const float* __restrict__ q,
                          const int*   __restrict__ idx_i,
                          const int*   __restrict__ idx_j,
                          const float* __restrict__ d_ij,
                          const int*   __restrict__ seg,
                          float*       __restrict__ out)
{
    __shared__ float acc[N_MOLS];   // 16 KB per-block private histogram

    // Vectorized zero (2 x STS.128 per thread)
    {
        float4* acc4 = reinterpret_cast<float4*>(acc);
        for (int m = threadIdx.x; m < N_MOLS / 4; m += blockDim.x)
            acc4[m] = make_float4(0.0f, 0.0f, 0.0f, 0.0f);
    }
    __syncthreads();

    const int nquads = N_PAIRS / 4;
    const int stride = gridDim.x * blockDim.x;

    for (int t = blockIdx.x * blockDim.x + threadIdx.x; t < nquads; t += stride) {
        // ---- Streaming loads (evict-first: keep L1 for gathers) ----
        int4   vi = __ldcs(reinterpret_cast<const int4*>(idx_i) + t);
        int4   vj = __ldcs(reinterpret_cast<const int4*>(idx_j) + t);
        float4 vd = __ldcs(reinterpret_cast<const float4*>(d_ij) + t);
        int4   vs = __ldcs(reinterpret_cast<const int4*>(seg)   + t);

        // ---- Batch the 8 random gathers back-to-back (max MLP) ----
        float qi0 = __ldg(q + vi.x), qj0 = __ldg(q + vj.x);
        float qi1 = __ldg(q + vi.y), qj1 = __ldg(q + vj.y);
        float qi2 = __ldg(q + vi.z), qj2 = __ldg(q + vj.z);
        float qi3 = __ldg(q + vi.w), qj3 = __ldg(q + vj.w);

        // ---- Compute ----
        float c0 = qi0 * qj0 * chi_of_d(vd.x);
        float c1 = qi1 * qj1 * chi_of_d(vd.y);
        float c2 = qi2 * qj2 * chi_of_d(vd.z);
        float c3 = qi3 * qj3 * chi_of_d(vd.w);

        // ---- Scatter: single-statement if -> @P ATOMS (no BSSY) ----
        if (vi.x < vj.x) atomicAdd(&acc[vs.x], c0);
        if (vi.y < vj.y) atomicAdd(&acc[vs.y], c1);
        if (vi.z < vj.z) atomicAdd(&acc[vs.z], c2);
        if (vi.w < vj.w) atomicAdd(&acc[vs.w], c3);
    }

    __syncthreads();

    // Flush block-private histogram (out already holds pse*KE).
    // Stagger the flush ORDER per block so concurrently-flushing blocks hit
    // DIFFERENT molecule addresses (decorrelated across LTS slices) instead
    // of marching through 0..4095 in lockstep and serializing per-address.
    const int base = (blockIdx.x * 64) & (N_MOLS - 1);
    for (int mm = threadIdx.x; mm < N_MOLS; mm += blockDim.x) {
        int m = (mm + base) & (N_MOLS - 1);   // stays coalesced per warp
        float v = acc[m];
        if (v != 0.0f)
            atomicAdd(&out[m], v * KE_CONST);
    }
}

// ---------------------------------------------------------------------------
// Launch
// ---------------------------------------------------------------------------
extern "C" void kernel_launch(void* const* d_in, const int* in_sizes, int n_in,
                              void* d_out, int out_size) {
    const float* q    = (const float*)d_in[0];           // per_atom_charge [N_ATOMS]
    const int*   pidx = (const int*)  d_in[1];           // pair_indices [2, N_PAIRS]
    const float* dij  = (const float*)d_in[2];           // d_ij [N_PAIRS]
    const int*   seg  = (const int*)  d_in[3];           // atomic_subsystem_indices [N_PAIRS]
    const float* pse  = (const float*)d_in[4];           // per_system_energy [N_MOLS]
    float* out = (float*)d_out;

    const int* idx_i = pidx;
    const int* idx_j = pidx + N_PAIRS;

    init_out_kernel<<<(N_MOLS + 255) / 256, 256>>>(pse, out);

    // Proven config: single wave, 4 blocks/SM x 148 SMs, 512 threads.
    const int blocks  = 592;
    const int threads = 512;
    coulomb_pairs_kernel<<<blocks, threads>>>(q, idx_i, idx_j, dij, seg, out);
}